// round 8
// baseline (speedup 1.0000x reference)
#include <cuda_runtime.h>

// SSIM loss, fused separable 11x11 gaussian blur + ssim map + mean reduce.
// R8 (base = R6 @238us, launch_bounds(256,6)):
//  - phase-2 output stored interleaved per pixel (stride 6 floats:
//    {m1,m2,q11,q22,q12,pad}) -> phase 3 does 3 loads (2xLDS.64+LDS.32)
//    per row-tap instead of 5 LDS.32: 39 vs 65 LDS/thread. Conflict-free
//    (24B col stride = 16 distinct banks per 64-bit phase).
//  - single main launch (one wave tail), epilogue 1 barrier (static wsum).
//  R7's launch_bounds(256,7) regression showed reg-cap sensitivity: stay at 6.

#define IMG      512
#define TW       32
#define TH       22
#define HALO     5
#define INW      42          // TW + 2*HALO
#define INWP     44          // padded row stride
#define INH      32          // TH + 2*HALO  (=> phase2 tasks = 32*8 = 256)
#define NT       256
#define FSTR     6           // interleaved field stride (floats)

#define GX       16          // 512/32
#define GY       24          // 24*22 = 528 rows, tail masked
#define PL       96
#define NB       (GX * GY * PL)   // 36864 = 36*1024

#define SMEM_FLOATS (2 * INH * INWP + INH * TW * FSTR)   // 2816 + 6144 = 8960
#define SMEM_BYTES  (SMEM_FLOATS * 4)                    // 35840

__device__ float g_part[NB];
__device__ float g_part2[36];

// 1D gaussian, sigma=1.5, K=11, normalized. Constant indices fold to
// FFMA immediates (rt_SMSP=1 imm-form).
__device__ __forceinline__ constexpr float gw(int k) {
    switch (k) {
        case 0:  return 0.00102838f;
        case 1:  return 0.00759877f;
        case 2:  return 0.03600077f;
        case 3:  return 0.10936069f;
        case 4:  return 0.21300554f;
        case 5:  return 0.26601173f;
        case 6:  return 0.21300554f;
        case 7:  return 0.10936069f;
        case 8:  return 0.03600077f;
        case 9:  return 0.00759877f;
        case 10: return 0.00102838f;
    }
    return 0.0f;
}

__global__ __launch_bounds__(NT, 6)
void ssim_main(const float* __restrict__ img1, const float* __restrict__ img2) {
    extern __shared__ float smem[];
    float* s1 = smem;                       // raw x1 tile [INH][INWP]
    float* s2 = smem + INH * INWP;          // raw x2 tile
    float* sh = smem + 2 * INH * INWP;      // interleaved fields [INH][TW][6]
    __shared__ float wsum[NT / 32];

    const int tid = threadIdx.x;
    const int gx0 = blockIdx.x * TW - HALO;
    const int gy0 = blockIdx.y * TH - HALO;
    const size_t pbase = (size_t)blockIdx.z * (IMG * IMG);
    const float* p1 = img1 + pbase;
    const float* p2 = img2 + pbase;

    // ---- Phase 1: global -> smem, (v+1)*0.5, zero-pad OOB ----
    {
        const int r  = tid >> 3;
        const int c  = tid & 7;
        const int gy = gy0 + r;
        const bool rowok = (gy >= 0) && (gy < IMG);
        const float* q1 = p1 + (size_t)gy * IMG;
        const float* q2 = p2 + (size_t)gy * IMG;
        #pragma unroll
        for (int k = 0; k < 6; k++) {
            int cc = c + 8 * k;
            if (k < 5 || cc < INWP) {
                int gx = gx0 + cc;
                float v1 = 0.f, v2 = 0.f;
                if (rowok && cc < INW && gx >= 0 && gx < IMG) {
                    v1 = fmaf(q1[gx], 0.5f, 0.5f);
                    v2 = fmaf(q2[gx], 0.5f, 0.5f);
                }
                s1[r * INWP + cc] = v1;
                s2[r * INWP + cc] = v2;
            }
        }
    }
    __syncthreads();

    // ---- Phase 2: horizontal 11-tap blur, exactly one task per thread ----
    {
        const int row = tid >> 3;
        const int c0  = (tid & 7) << 2;

        float a[16], b[16];
        {
            const float4* a4 = (const float4*)(s1 + row * INWP + c0);
            const float4* b4 = (const float4*)(s2 + row * INWP + c0);
            ((float4*)a)[0] = a4[0]; ((float4*)a)[1] = a4[1];
            ((float4*)a)[2] = a4[2]; ((float4*)a)[3] = a4[3];
            ((float4*)b)[0] = b4[0]; ((float4*)b)[1] = b4[1];
            ((float4*)b)[2] = b4[2]; ((float4*)b)[3] = b4[3];
        }

        float m1[4]  = {0.f, 0.f, 0.f, 0.f};
        float m2[4]  = {0.f, 0.f, 0.f, 0.f};
        float q11[4] = {0.f, 0.f, 0.f, 0.f};
        float q22[4] = {0.f, 0.f, 0.f, 0.f};
        float q12[4] = {0.f, 0.f, 0.f, 0.f};

        #pragma unroll
        for (int i = 0; i < 14; i++) {
            float fa = a[i], fb = b[i];
            float faa = fa * fa, fbb = fb * fb, fab = fa * fb;
            #pragma unroll
            for (int j = 0; j < 4; j++) {
                int k = i - j;
                if (k >= 0 && k < 11) {
                    float w = gw(k);
                    m1[j]  = fmaf(fa,  w, m1[j]);
                    m2[j]  = fmaf(fb,  w, m2[j]);
                    q11[j] = fmaf(faa, w, q11[j]);
                    q22[j] = fmaf(fbb, w, q22[j]);
                    q12[j] = fmaf(fab, w, q12[j]);
                }
            }
        }

        // interleaved store: [row][col][{m1,m2,q11,q22,q12,pad}]
        #pragma unroll
        for (int j = 0; j < 4; j++) {
            float* hb = sh + (row * TW + c0 + j) * FSTR;
            *(float2*)(hb + 0) = make_float2(m1[j],  m2[j]);
            *(float2*)(hb + 2) = make_float2(q11[j], q22[j]);
            hb[4] = q12[j];
        }
    }
    __syncthreads();

    // ---- Phase 3: vertical blur + ssim. groups 0-5: 3 rows, 6-7: 2 rows ----
    const int col = tid & 31;
    const int g   = tid >> 5;
    const int r_start = (g < 6) ? 3 * g : 18 + 2 * (g - 6);

    float acc0[3], acc1[3], acc2[3], acc3[3], acc4[3];
    #pragma unroll
    for (int j = 0; j < 3; j++) {
        acc0[j] = 0.f; acc1[j] = 0.f; acc2[j] = 0.f; acc3[j] = 0.f; acc4[j] = 0.f;
    }

    #pragma unroll
    for (int i = 0; i < 13; i++) {
        int ri = r_start + i;
        if (ri > INH - 1) ri = INH - 1;   // only dead lanes hit clamp
        const float* hp = sh + (ri * TW + col) * FSTR;
        float2 v01 = *(const float2*)(hp + 0);
        float2 v23 = *(const float2*)(hp + 2);
        float  v4  = hp[4];
        #pragma unroll
        for (int j = 0; j < 3; j++) {
            int k = i - j;
            if (k >= 0 && k < 11) {
                float w = gw(k);
                acc0[j] = fmaf(v01.x, w, acc0[j]);
                acc1[j] = fmaf(v01.y, w, acc1[j]);
                acc2[j] = fmaf(v23.x, w, acc2[j]);
                acc3[j] = fmaf(v23.y, w, acc3[j]);
                acc4[j] = fmaf(v4,    w, acc4[j]);
            }
        }
    }

    const float C1 = 0.0001f;   // 0.01^2
    const float C2 = 0.0009f;   // 0.03^2
    const int   gyb = blockIdx.y * TH + r_start;
    float tsum = 0.f;
    #pragma unroll
    for (int j = 0; j < 3; j++) {
        bool valid = (j < 2 || g < 6) && (gyb + j < IMG);
        if (valid) {
            float mu1 = acc0[j], mu2 = acc1[j];
            float mu1s = mu1 * mu1, mu2s = mu2 * mu2, mu12 = mu1 * mu2;
            float sA  = acc2[j] - mu1s;
            float sB  = acc3[j] - mu2s;
            float sAB = acc4[j] - mu12;
            float num = (2.f * mu12 + C1) * (2.f * sAB + C2);
            float den = (mu1s + mu2s + C1) * (sA + sB + C2);
            tsum += __fdividef(num, den);
        }
    }

    // ---- Reduction: warp shuffle -> static wsum (1 barrier) -> STG ----
    #pragma unroll
    for (int off = 16; off; off >>= 1)
        tsum += __shfl_xor_sync(0xffffffffu, tsum, off);

    if ((tid & 31) == 0) wsum[tid >> 5] = tsum;
    __syncthreads();
    if (tid == 0) {
        float bs = 0.f;
        #pragma unroll
        for (int i = 0; i < NT / 32; i++) bs += wsum[i];
        int slot = (blockIdx.z * GY + blockIdx.y) * GX + blockIdx.x;
        g_part[slot] = bs;
    }
}

__global__ __launch_bounds__(1024)
void ssim_reduce1() {
    __shared__ float ws[32];
    const int tid = threadIdx.x;
    float s = g_part[blockIdx.x * 1024 + tid];

    #pragma unroll
    for (int off = 16; off; off >>= 1)
        s += __shfl_xor_sync(0xffffffffu, s, off);
    if ((tid & 31) == 0) ws[tid >> 5] = s;
    __syncthreads();
    if (tid < 32) {
        float t = ws[tid];
        #pragma unroll
        for (int off = 16; off; off >>= 1)
            t += __shfl_xor_sync(0xffffffffu, t, off);
        if (tid == 0) g_part2[blockIdx.x] = t;
    }
}

__global__ void ssim_fin(float* out, double inv_n) {
    const int tid = threadIdx.x;   // 32 threads
    double s = (double)g_part2[tid];
    if (tid < 4) s += (double)g_part2[tid + 32];
    #pragma unroll
    for (int off = 16; off; off >>= 1)
        s += __shfl_xor_sync(0xffffffffu, s, off);
    if (tid == 0) out[0] = 1.0f - (float)(s * inv_n);
}

extern "C" void kernel_launch(void* const* d_in, const int* in_sizes, int n_in,
                              void* d_out, int out_size) {
    const float* img1 = (const float*)d_in[0];
    const float* img2 = (const float*)d_in[1];
    (void)n_in; (void)out_size; (void)in_sizes;

    cudaFuncSetAttribute(ssim_main, cudaFuncAttributeMaxDynamicSharedMemorySize,
                         SMEM_BYTES);

    dim3 grid(GX, GY, PL);
    ssim_main<<<grid, NT, SMEM_BYTES>>>(img1, img2);

    ssim_reduce1<<<36, 1024>>>();
    double inv_n = 1.0 / ((double)PL * IMG * IMG);
    ssim_fin<<<1, 32>>>((float*)d_out, inv_n);
}